// round 5
// baseline (speedup 1.0000x reference)
#include <cuda_runtime.h>
#include <cuda_bf16.h>
#include <cstdint>

// GraphSAGE 2-layer, D=64, fp32 — CSR gather v2 (shuffle-broadcast) + f32x2 combine.
//
//   layer: out = h @ W_self + mean_{in}(h) @ W_neigh + b
//   h1 = relu(layer1(x)); out = layer2(h1)
//
// Launch sequence (8 kernels, no runtime API calls, graph-capturable):
//   1 zero_cnt  2 hist(+rank)  3 scan  4 fill(no atomics)
//   5 gather<x>  6 combine(relu,->h1)  7 gather<h1>  8 combine(->out)

#define D 64
#define MAXN 50048
#define MAXE 850000
#define SCAN_THREADS 1024

__device__ float g_mean[MAXN * D];    // gather writes neighbor MEAN rows
__device__ float g_h1[MAXN * D];      // layer-1 activations
__device__ int   g_cnt[MAXN];         // in-degree (histogram)
__device__ int   g_rowstart[MAXN];    // CSR exclusive offsets
__device__ int   g_rank[MAXE];        // per-edge rank within its dst row
__device__ int   g_edge[MAXE];        // CSR column (src) indices

typedef unsigned long long u64;

__device__ __forceinline__ u64 pk2(float a, float b) {
    u64 r;
    asm("mov.b64 %0, {%1, %2};" : "=l"(r)
        : "r"(__float_as_uint(a)), "r"(__float_as_uint(b)));
    return r;
}
__device__ __forceinline__ void upk2(u64 v, float& a, float& b) {
    unsigned int x, y;
    asm("mov.b64 {%0, %1}, %2;" : "=r"(x), "=r"(y) : "l"(v));
    a = __uint_as_float(x);
    b = __uint_as_float(y);
}
__device__ __forceinline__ u64 fma2(u64 a, u64 b, u64 c) {
    u64 d;
    asm("fma.rn.f32x2 %0, %1, %2, %3;" : "=l"(d) : "l"(a), "l"(b), "l"(c));
    return d;
}

// ---------------------------------------------------------------------------
__global__ void zero_cnt_kernel(int n) {
    int i = blockIdx.x * blockDim.x + threadIdx.x;
    if (i < n) g_cnt[i] = 0;
}

// Histogram + capture each edge's arrival rank (makes fill atomic-free).
__global__ void hist_kernel(const int* __restrict__ dst, int E) {
    int e = blockIdx.x * blockDim.x + threadIdx.x;
    if (e < E) g_rank[e] = atomicAdd(&g_cnt[__ldg(dst + e)], 1);
}

// Single-block exclusive scan of g_cnt -> g_rowstart.
__global__ void __launch_bounds__(SCAN_THREADS)
scan_kernel(int n) {
    __shared__ int s[SCAN_THREADS];
    int t = threadIdx.x;
    int items = (n + SCAN_THREADS - 1) / SCAN_THREADS;
    int lo = t * items;
    int hi = min(n, lo + items);

    int sum = 0;
    for (int i = lo; i < hi; i++) sum += g_cnt[i];
    s[t] = sum;
    __syncthreads();
    for (int off = 1; off < SCAN_THREADS; off <<= 1) {
        int v = (t >= off) ? s[t - off] : 0;
        __syncthreads();
        s[t] += v;
        __syncthreads();
    }
    int base = (t == 0) ? 0 : s[t - 1];
    for (int i = lo; i < hi; i++) {
        g_rowstart[i] = base;
        base += g_cnt[i];
    }
}

// Atomic-free fill: slot = rowstart[dst] + rank.
__global__ void fill_kernel(const int* __restrict__ src,
                            const int* __restrict__ dst, int E) {
    int e = blockIdx.x * blockDim.x + threadIdx.x;
    if (e < E) {
        int d = __ldg(dst + e);
        g_edge[g_rowstart[d] + g_rank[e]] = __ldg(src + e);
    }
}

// ---------------------------------------------------------------------------
// Gather v2: warp per node. Load up to 32 edge indices in ONE coalesced LDG
// (one per lane), shuffle-broadcast, then issue all row loads independently
// (MLP ~ deg). Lane owns float2 at column lane*2. Writes the MEAN row.
// ---------------------------------------------------------------------------
template <bool FROM_H1>
__global__ void __launch_bounds__(256)
gather_kernel(const float* __restrict__ h_in, int n) {
    const float* __restrict__ h = FROM_H1 ? (const float*)g_h1 : h_in;

    int warp = (blockIdx.x * blockDim.x + threadIdx.x) >> 5;
    if (warp >= n) return;
    int lane = threadIdx.x & 31;

    int start = g_rowstart[warp];
    int deg   = g_cnt[warp];

    const float2* __restrict__ base = reinterpret_cast<const float2*>(h);
    float ax = 0.f, ay = 0.f;

    for (int j0 = 0; j0 < deg; j0 += 32) {
        int nj = min(32, deg - j0);
        int myidx = (lane < nj) ? __ldg(g_edge + start + j0 + lane) : 0;

        int j = 0;
        // 4-wide stripes: shfl 4 indices, fire 4 independent row loads.
        for (; j + 4 <= nj; j += 4) {
            int s0 = __shfl_sync(0xffffffffu, myidx, j + 0);
            int s1 = __shfl_sync(0xffffffffu, myidx, j + 1);
            int s2 = __shfl_sync(0xffffffffu, myidx, j + 2);
            int s3 = __shfl_sync(0xffffffffu, myidx, j + 3);
            float2 v0 = __ldg(base + (size_t)s0 * 32 + lane);
            float2 v1 = __ldg(base + (size_t)s1 * 32 + lane);
            float2 v2 = __ldg(base + (size_t)s2 * 32 + lane);
            float2 v3 = __ldg(base + (size_t)s3 * 32 + lane);
            ax += v0.x + v1.x + v2.x + v3.x;
            ay += v0.y + v1.y + v2.y + v3.y;
        }
        for (; j < nj; j++) {
            int s = __shfl_sync(0xffffffffu, myidx, j);
            float2 v = __ldg(base + (size_t)s * 32 + lane);
            ax += v.x; ay += v.y;
        }
    }

    float inv = 1.0f / fmaxf((float)deg, 1.0f);
    float2 m; m.x = ax * inv; m.y = ay * inv;
    reinterpret_cast<float2*>(g_mean)[(size_t)warp * 32 + lane] = m;
}

// ---------------------------------------------------------------------------
// Combine (R4 design): out = h@W_self + mean@W_neigh + b [+relu]
// 256 threads = 16 col-groups x 16 node-groups of 4 nodes; f32x2 FMAs.
// ---------------------------------------------------------------------------
template <bool RELU, bool FROM_H1, bool TO_H1>
__global__ void __launch_bounds__(256, 2)
combine_kernel(const float* __restrict__ h_in,
               const float* __restrict__ Wself,
               const float* __restrict__ Wneigh,
               const float* __restrict__ bias,
               float* __restrict__ out_in, int n) {
    const float* __restrict__ h = FROM_H1 ? (const float*)g_h1 : h_in;
    float* __restrict__ out     = TO_H1 ? (float*)g_h1 : out_in;

    __shared__ float sWs[D * D];
    __shared__ float sWn[D * D];

    int tid = threadIdx.x;
    for (int i = tid; i < D * D / 4; i += 256) {
        reinterpret_cast<float4*>(sWs)[i] =
            reinterpret_cast<const float4*>(Wself)[i];
        reinterpret_cast<float4*>(sWn)[i] =
            reinterpret_cast<const float4*>(Wneigh)[i];
    }
    __syncthreads();

    int cg = tid & 15;
    int c0 = cg * 4;
    int ng = tid >> 4;
    int nbase = blockIdx.x * 64 + ng * 4;

    bool valid[4];
#pragma unroll
    for (int i = 0; i < 4; i++) valid[i] = (nbase + i) < n;

    u64 b01 = pk2(__ldg(bias + c0 + 0), __ldg(bias + c0 + 1));
    u64 b23 = pk2(__ldg(bias + c0 + 2), __ldg(bias + c0 + 3));

    u64 acc[4][2];
#pragma unroll
    for (int i = 0; i < 4; i++) { acc[i][0] = b01; acc[i][1] = b23; }

#pragma unroll 4
    for (int k0 = 0; k0 < D; k0 += 4) {
        float4 xv[4], mv[4];
#pragma unroll
        for (int i = 0; i < 4; i++) {
            if (valid[i]) {
                xv[i] = *reinterpret_cast<const float4*>(
                    h + (size_t)(nbase + i) * D + k0);
                mv[i] = *reinterpret_cast<const float4*>(
                    g_mean + (size_t)(nbase + i) * D + k0);
            } else {
                xv[i] = make_float4(0.f, 0.f, 0.f, 0.f);
                mv[i] = make_float4(0.f, 0.f, 0.f, 0.f);
            }
        }

#pragma unroll
        for (int j = 0; j < 4; j++) {
            int k = k0 + j;
            float4 ws = *reinterpret_cast<const float4*>(sWs + k * D + c0);
            float4 wn = *reinterpret_cast<const float4*>(sWn + k * D + c0);
            u64 ws01 = pk2(ws.x, ws.y), ws23 = pk2(ws.z, ws.w);
            u64 wn01 = pk2(wn.x, wn.y), wn23 = pk2(wn.z, wn.w);
#pragma unroll
            for (int i = 0; i < 4; i++) {
                float xk = (j == 0) ? xv[i].x : (j == 1) ? xv[i].y
                          : (j == 2) ? xv[i].z : xv[i].w;
                float mk = (j == 0) ? mv[i].x : (j == 1) ? mv[i].y
                          : (j == 2) ? mv[i].z : mv[i].w;
                u64 xx = pk2(xk, xk);
                u64 mm = pk2(mk, mk);
                acc[i][0] = fma2(xx, ws01, acc[i][0]);
                acc[i][0] = fma2(mm, wn01, acc[i][0]);
                acc[i][1] = fma2(xx, ws23, acc[i][1]);
                acc[i][1] = fma2(mm, wn23, acc[i][1]);
            }
        }
    }

#pragma unroll
    for (int i = 0; i < 4; i++) {
        if (!valid[i]) continue;
        float a0, a1, a2, a3;
        upk2(acc[i][0], a0, a1);
        upk2(acc[i][1], a2, a3);
        if (RELU) {
            a0 = fmaxf(a0, 0.f); a1 = fmaxf(a1, 0.f);
            a2 = fmaxf(a2, 0.f); a3 = fmaxf(a3, 0.f);
        }
        *reinterpret_cast<float4*>(out + (size_t)(nbase + i) * D + c0) =
            make_float4(a0, a1, a2, a3);
    }
}

// ---------------------------------------------------------------------------
extern "C" void kernel_launch(void* const* d_in, const int* in_sizes, int n_in,
                              void* d_out, int out_size) {
    const float* x        = (const float*)d_in[0];
    const int*   src      = (const int*)d_in[1];
    const int*   dst      = (const int*)d_in[2];
    const float* W1_self  = (const float*)d_in[3];
    const float* W1_neigh = (const float*)d_in[4];
    const float* b1       = (const float*)d_in[5];
    const float* W2_self  = (const float*)d_in[6];
    const float* W2_neigh = (const float*)d_in[7];
    const float* b2       = (const float*)d_in[8];
    float* out = (float*)d_out;

    int n = in_sizes[0] / D;
    int E = in_sizes[1];

    int eb = (E + 255) / 256;
    int nb = (n + 255) / 256;
    int gb = (n * 32 + 255) / 256;     // warp per node
    int cb = (n + 63) / 64;

    // ---- CSR build (shared by both layers) ----
    zero_cnt_kernel<<<nb, 256>>>(n);
    hist_kernel<<<eb, 256>>>(dst, E);
    scan_kernel<<<1, SCAN_THREADS>>>(n);
    fill_kernel<<<eb, 256>>>(src, dst, E);

    // ---- layer 1 ----  (x -> g_h1, relu)
    gather_kernel<false><<<gb, 256>>>(x, n);
    combine_kernel<true, false, true>
        <<<cb, 256>>>(x, W1_self, W1_neigh, b1, nullptr, n);

    // ---- layer 2 ----  (g_h1 -> out)
    gather_kernel<true><<<gb, 256>>>(nullptr, n);
    combine_kernel<false, true, false>
        <<<cb, 256>>>(nullptr, W2_self, W2_neigh, b2, out, n);
}